// round 15
// baseline (speedup 1.0000x reference)
#include <cuda_runtime.h>
#include <cuda_fp16.h>
#include <cstdint>
#include <cstddef>

#define NN   50000
#define EE   400000
#define DDIM 512
#define DOUT 128
#define SCAN_B 512

// ---------------------------------------------------------------------------
// Scratch (device globals: allocation-free rule)
__device__ __half g_x  [(size_t)NN * DDIM];
__device__ __half g_a  [(size_t)NN * DDIM];
__device__ __half g_h1 [(size_t)NN * DDIM];
__device__ __half g_h2 [(size_t)NN * DDIM];
__device__ __half g_cs [(size_t)NN * DDIM];   // fp16 self-term scratch
// Transposed weights [N][K] fp16
__device__ __half g_w1l[512*512];
__device__ __half g_w1r[512*512];
__device__ __half g_w2l[512*512];
__device__ __half g_w2r[512*512];
__device__ __half g_w3l[128*512];
__device__ __half g_w3r[128*512];
// CSR
__device__ int g_deg[NN];
__device__ int g_rowptr[NN + 1];
__device__ int g_cursor[NN];
__device__ int g_csr[EE];
__device__ int g_bsums[(NN + SCAN_B - 1) / SCAN_B + 1];

// ---------------------------------------------------------------------------
// PTX helpers (base-arch only: ldmatrix / mma.sync / cp.async)
// ---------------------------------------------------------------------------
__device__ __forceinline__ uint32_t smem_to_u32(const void* p) {
    uint32_t a;
    asm("{ .reg .u64 t; cvta.to.shared.u64 t, %1; cvt.u32.u64 %0, t; }"
        : "=r"(a) : "l"(p));
    return a;
}

#define LDSM_X4(r0, r1, r2, r3, addr) \
    asm volatile("ldmatrix.sync.aligned.m8n8.x4.shared.b16 {%0,%1,%2,%3}, [%4];" \
        : "=r"(r0), "=r"(r1), "=r"(r2), "=r"(r3) : "r"(addr))

#define MMA_FP16(c, a, bv0, bv1) \
    asm volatile("mma.sync.aligned.m16n8k16.row.col.f32.f16.f16.f32 " \
        "{%0,%1,%2,%3}, {%4,%5,%6,%7}, {%8,%9}, {%0,%1,%2,%3};" \
        : "+f"((c)[0]), "+f"((c)[1]), "+f"((c)[2]), "+f"((c)[3]) \
        : "r"((a)[0]), "r"((a)[1]), "r"((a)[2]), "r"((a)[3]), "r"(bv0), "r"(bv1))

#define CP_ASYNC16(smem, gmem, sz) \
    asm volatile("cp.async.cg.shared.global [%0], [%1], 16, %2;" \
        :: "r"(smem), "l"(gmem), "r"(sz) : "memory")
#define CP_COMMIT() asm volatile("cp.async.commit_group;" ::: "memory")
#define CP_WAIT(n)  asm volatile("cp.async.wait_group %0;" :: "n"(n) : "memory")

// ---------------------------------------------------------------------------
// fp16 helpers
// ---------------------------------------------------------------------------
__device__ __forceinline__ uint32_t pack_h2(float a, float b) {
    __half2 t = __floats2half2_rn(a, b);
    return *reinterpret_cast<uint32_t*>(&t);
}
__device__ __forceinline__ float2 unpack_h2(uint32_t u) {
    __half2 t = *reinterpret_cast<__half2*>(&u);
    return __half22float2(t);
}

// ---------------------------------------------------------------------------
// prep: convx + weight transposes (NO zeroing here — that lives on the CSR
// stream so the two branches are fully independent).
// ---------------------------------------------------------------------------
#define CONVB  2048
#define WCONVB 1152

__global__ void prep_kernel(const float4* __restrict__ x, uint2* __restrict__ xh,
                            int n4,
                            const float* __restrict__ W1l, const float* __restrict__ W1r,
                            const float* __restrict__ W2l, const float* __restrict__ W2r,
                            const float* __restrict__ W3l, const float* __restrict__ W3r,
                            __half* __restrict__ o1l, __half* __restrict__ o1r,
                            __half* __restrict__ o2l, __half* __restrict__ o2r,
                            __half* __restrict__ o3l, __half* __restrict__ o3r) {
    __shared__ float t[32][33];
    const int b = blockIdx.x;
    const int tid = threadIdx.x;
    if (b < CONVB) {
        int i = b * 256 + tid;
        const int stride = CONVB * 256;
        for (; i < n4; i += stride) {
            float4 v = x[i];
            uint2 u;
            u.x = pack_h2(v.x, v.y);
            u.y = pack_h2(v.z, v.w);
            xh[i] = u;
        }
    } else {
        int wb = b - CONVB;
        const float* W; __half* O; int N, idx;
        if (wb < 1024) {
            int z = wb >> 8; idx = wb & 255; N = 512;
            W = (z == 0) ? W1l : (z == 1) ? W1r : (z == 2) ? W2l : W2r;
            O = (z == 0) ? o1l : (z == 1) ? o1r : (z == 2) ? o2l : o2r;
        } else {
            int wb2 = wb - 1024; int z = wb2 >> 6; idx = wb2 & 63; N = 128;
            W = z ? W3r : W3l;
            O = z ? o3r : o3l;
        }
        const int nXb = N >> 5;
        int nb = (idx % nXb) * 32, kb = (idx / nXb) * 32;
        int tx = tid & 31, ty = tid >> 5;
        for (int i = ty; i < 32; i += 8)
            t[i][tx] = W[(size_t)(kb + i) * N + nb + tx];
        __syncthreads();
        for (int i = ty; i < 32; i += 8) {
            float v = t[tx][i];
            O[(size_t)(nb + i) * 512 + kb + tx] = __float2half_rn(v);
        }
    }
}

// ---------------------------------------------------------------------------
// CSR construction (self-contained branch: zeroing included)
// ---------------------------------------------------------------------------
__global__ void zero2_kernel(int* __restrict__ p1, int* __restrict__ p2, int n) {
    int i = blockIdx.x * blockDim.x + threadIdx.x;
    if (i < n) { p1[i] = 0; p2[i] = 0; }
}
__global__ void deg_kernel(const int* __restrict__ dst, int* __restrict__ deg, int E) {
    int e = blockIdx.x * blockDim.x + threadIdx.x;
    if (e < E) atomicAdd(&deg[dst[e]], 1);
}
__global__ void scan1_kernel(const int* __restrict__ deg, int* __restrict__ rowptr,
                             int* __restrict__ bsums, int M) {
    __shared__ int sh[SCAN_B];
    int tid = threadIdx.x;
    int i = blockIdx.x * SCAN_B + tid;
    int v = (i < M) ? deg[i] : 0;
    sh[tid] = v;
    __syncthreads();
#pragma unroll
    for (int off = 1; off < SCAN_B; off <<= 1) {
        int t = (tid >= off) ? sh[tid - off] : 0;
        __syncthreads();
        sh[tid] += t;
        __syncthreads();
    }
    if (i < M) rowptr[i] = sh[tid] - v;
    if (tid == SCAN_B - 1) bsums[blockIdx.x] = sh[tid];
}
__global__ void scan3_kernel(int* __restrict__ rowptr, const int* __restrict__ bsums,
                             int nblk, int M) {
    __shared__ int sh[256];
    const int tid = threadIdx.x;
    const int chunk = blockIdx.x >> 1;
    int partial = 0;
    for (int j = tid; j < chunk; j += 256) partial += bsums[j];
    sh[tid] = partial;
    __syncthreads();
#pragma unroll
    for (int off = 128; off; off >>= 1) {
        if (tid < off) sh[tid] += sh[tid + off];
        __syncthreads();
    }
    const int off = sh[0];
    int i = blockIdx.x * 256 + tid;
    if (i < M) rowptr[i] += off;
    if (blockIdx.x == 0 && tid == 0) {
        int tot = 0;
        for (int j = 0; j < nblk; j++) tot += bsums[j];
        rowptr[M] = tot;
    }
}
__global__ void csr_fill_kernel(const int* __restrict__ src, const int* __restrict__ dst,
                                const int* __restrict__ rowptr, int* __restrict__ cursor,
                                int* __restrict__ csr, int E) {
    int e = blockIdx.x * blockDim.x + threadIdx.x;
    if (e < E) {
        int d = dst[e];
        int pos = atomicAdd(&cursor[d], 1);
        csr[rowptr[d] + pos] = src[e];
    }
}

// ---------------------------------------------------------------------------
// Gather-mean on fp16: 4 nodes per block, 64 threads per node,
// one uint4 (8 halves) per thread; 8-deep unroll.
// ---------------------------------------------------------------------------
__global__ void gather_mean_kernel(const __half* __restrict__ xh,
                                   const int* __restrict__ rowptr,
                                   const int* __restrict__ csr,
                                   __half* __restrict__ ah, int M) {
    int node = blockIdx.x * 4 + (threadIdx.x >> 6);
    int t    = threadIdx.x & 63;
    if (node >= M) return;
    int beg = rowptr[node], end = rowptr[node + 1];
    const uint4* XH = (const uint4*)xh;
    float a[8];
#pragma unroll
    for (int j = 0; j < 8; j++) a[j] = 0.f;

    auto accum = [&](uint4 u) {
        float2 p;
        p = unpack_h2(u.x); a[0] += p.x; a[1] += p.y;
        p = unpack_h2(u.y); a[2] += p.x; a[3] += p.y;
        p = unpack_h2(u.z); a[4] += p.x; a[5] += p.y;
        p = unpack_h2(u.w); a[6] += p.x; a[7] += p.y;
    };

    int i = beg;
    for (; i + 7 < end; i += 8) {
        uint4 v0 = XH[(size_t)csr[i+0] * 64 + t];
        uint4 v1 = XH[(size_t)csr[i+1] * 64 + t];
        uint4 v2 = XH[(size_t)csr[i+2] * 64 + t];
        uint4 v3 = XH[(size_t)csr[i+3] * 64 + t];
        uint4 v4 = XH[(size_t)csr[i+4] * 64 + t];
        uint4 v5 = XH[(size_t)csr[i+5] * 64 + t];
        uint4 v6 = XH[(size_t)csr[i+6] * 64 + t];
        uint4 v7 = XH[(size_t)csr[i+7] * 64 + t];
        accum(v0); accum(v1); accum(v2); accum(v3);
        accum(v4); accum(v5); accum(v6); accum(v7);
    }
    for (; i + 3 < end; i += 4) {
        uint4 v0 = XH[(size_t)csr[i+0] * 64 + t];
        uint4 v1 = XH[(size_t)csr[i+1] * 64 + t];
        uint4 v2 = XH[(size_t)csr[i+2] * 64 + t];
        uint4 v3 = XH[(size_t)csr[i+3] * 64 + t];
        accum(v0); accum(v1); accum(v2); accum(v3);
    }
    for (; i < end; i++) accum(XH[(size_t)csr[i] * 64 + t]);

    float inv = 1.0f / (float)max(end - beg, 1);
    uint4 u;
    uint32_t* pu = (uint32_t*)&u;
#pragma unroll
    for (int j = 0; j < 4; j++)
        pu[j] = pack_h2(a[j*2+0] * inv, a[j*2+1] * inv);
    ((uint4*)ah)[(size_t)node * 64 + t] = u;
}

// ---------------------------------------------------------------------------
// mma.sync fp16 GEMM, K=512 (8 chunks), 3-stage cp.async pipeline.
// CTA tile 128x128, 8 warps (4m x 2n), fp32 accumulators.
// MODE 0 (SELF):      C = A@B^T                  -> fp16 Ch (raw product)
// MODE 1 (COMB_RELU): C = A@B^T + Cs + bias,ReLU -> fp16 Ch
// MODE 2 (COMB_F32):  C = A@B^T + Cs + bias      -> fp32 Cf
// ---------------------------------------------------------------------------
template <int MODE>
__global__ __launch_bounds__(256, 2)
void gemm_mma(const __half* __restrict__ A, const __half* __restrict__ B,
              const float* __restrict__ bias, const __half* __restrict__ Cs,
              float* __restrict__ Cf, __half* __restrict__ Ch,
              int M, int Ntot) {
    extern __shared__ char dsm[];
    constexpr int SROW  = 144;
    constexpr int PLANE = 128 * SROW;  // 18432 B
    constexpr int STAGE = 2 * PLANE;   // 36864 B: A, B
    constexpr int NSTAGE = 3;          // 110592 B -> 2 CTAs/SM
    constexpr int OFF_A = 0, OFF_B = PLANE;
    constexpr int NCH = 8;             // K = 512

    const int tid  = threadIdx.x;
    const int wid  = tid >> 5;
    const int lane = tid & 31;
    const int wm = wid >> 1;
    const int wn = wid & 1;
    const int mBase = blockIdx.y * 128;
    const int nBase = blockIdx.x * 128;
    const uint32_t smem = smem_to_u32(dsm);

    auto issue_chunk = [&](int ch, int s) {
        const int k0b = ch * 128;
        const uint32_t sb = smem + s * STAGE;
#pragma unroll
        for (int it = 0; it < 4; it++) {
            int c = tid + it * 256;
            int row = c >> 3, q = c & 7;
            uint32_t soff = row * SROW + q * 16;
            int am = mBase + row;
            int asz = (am < M) ? 16 : 0;
            size_t ga = (size_t)(am < M ? am : 0) * 1024 + k0b + q * 16;
            CP_ASYNC16(sb + OFF_A + soff, (const char*)A + ga, asz);
            size_t gb = (size_t)(nBase + row) * 1024 + k0b + q * 16;
            CP_ASYNC16(sb + OFF_B + soff, (const char*)B + gb, 16);
        }
        CP_COMMIT();
    };

    float acc[2][8][4];
#pragma unroll
    for (int i = 0; i < 2; i++)
#pragma unroll
        for (int j = 0; j < 8; j++)
#pragma unroll
            for (int k = 0; k < 4; k++) acc[i][j][k] = 0.f;

    const int g = lane >> 3, r = lane & 7;

    issue_chunk(0, 0);
    issue_chunk(1, 1);
    for (int ch = 0; ch < NCH; ch++) {
        const int s = ch % NSTAGE;
        if (ch + 1 < NCH) { CP_WAIT(1); } else { CP_WAIT(0); }
        __syncthreads();
        if (ch + 2 < NCH) issue_chunk(ch + 2, (ch + 2) % NSTAGE);

        const uint32_t sA = smem + s * STAGE + OFF_A;
        const uint32_t sB = smem + s * STAGE + OFF_B;

#pragma unroll
        for (int ks = 0; ks < 4; ks++) {
            uint32_t ah[2][4];
#pragma unroll
            for (int mi = 0; mi < 2; mi++) {
                uint32_t arow = wm * 32 + mi * 16 + ((g & 1) << 3) + r;
                uint32_t aoff = arow * SROW + ks * 32 + (g >> 1) * 16;
                LDSM_X4(ah[mi][0], ah[mi][1], ah[mi][2], ah[mi][3], sA + aoff);
            }
#pragma unroll
            for (int j = 0; j < 4; j++) {
                uint32_t brow = wn * 64 + j * 16 + ((g >> 1) << 3) + r;
                uint32_t boff = brow * SROW + ks * 32 + (g & 1) * 16;
                uint32_t b0, b1, b2, b3;
                LDSM_X4(b0, b1, b2, b3, sB + boff);
                MMA_FP16(acc[0][j*2+0], ah[0], b0, b1);
                MMA_FP16(acc[0][j*2+1], ah[0], b2, b3);
                MMA_FP16(acc[1][j*2+0], ah[1], b0, b1);
                MMA_FP16(acc[1][j*2+1], ah[1], b2, b3);
            }
        }
    }

    // ---- Epilogue ----
    const int qrow = lane >> 2, qcol = lane & 3;
#pragma unroll
    for (int mi = 0; mi < 2; mi++) {
#pragma unroll
        for (int ni = 0; ni < 8; ni++) {
            int row0 = mBase + wm * 32 + mi * 16 + qrow;
            int col  = nBase + wn * 64 + ni * 8 + qcol * 2;
#pragma unroll
            for (int h = 0; h < 2; h++) {
                int row = row0 + h * 8;
                if (row >= M) continue;
                float v0 = acc[mi][ni][h*2+0];
                float v1 = acc[mi][ni][h*2+1];
                if (MODE == 0) {
                    *(uint32_t*)(Ch + (size_t)row * Ntot + col) = pack_h2(v0, v1);
                } else {
                    float2 cs = unpack_h2(*(const uint32_t*)(Cs + (size_t)row * Ntot + col));
                    float2 bb = *(const float2*)(bias + col);
                    v0 += cs.x + bb.x;
                    v1 += cs.y + bb.y;
                    if (MODE == 1) {
                        v0 = fmaxf(v0, 0.f); v1 = fmaxf(v1, 0.f);
                        *(uint32_t*)(Ch + (size_t)row * Ntot + col) = pack_h2(v0, v1);
                    } else {
                        float2 o; o.x = v0; o.y = v1;
                        *(float2*)(Cf + (size_t)row * Ntot + col) = o;
                    }
                }
            }
        }
    }
}

// ---------------------------------------------------------------------------
// In-place log_softmax over rows of 128, one warp per row.
// ---------------------------------------------------------------------------
__global__ void log_softmax128_kernel(float* __restrict__ out, int M) {
    int row  = blockIdx.x * (blockDim.x >> 5) + (threadIdx.x >> 5);
    int lane = threadIdx.x & 31;
    if (row >= M) return;
    float4* p = (float4*)(out + (size_t)row * DOUT);
    float4 v = p[lane];
    float mx = fmaxf(fmaxf(v.x, v.y), fmaxf(v.z, v.w));
#pragma unroll
    for (int o = 16; o; o >>= 1) mx = fmaxf(mx, __shfl_xor_sync(0xffffffffu, mx, o));
    float s = expf(v.x - mx) + expf(v.y - mx) + expf(v.z - mx) + expf(v.w - mx);
#pragma unroll
    for (int o = 16; o; o >>= 1) s += __shfl_xor_sync(0xffffffffu, s, o);
    float l = mx + logf(s);
    v.x -= l; v.y -= l; v.z -= l; v.w -= l;
    p[lane] = v;
}

// ---------------------------------------------------------------------------
extern "C" void kernel_launch(void* const* d_in, const int* in_sizes, int n_in,
                              void* d_out, int out_size) {
    const float* x   = (const float*)d_in[0];
    const int*   ei  = (const int*)  d_in[1];
    const float* W1l = (const float*)d_in[2];
    const float* b1  = (const float*)d_in[3];
    const float* W1r = (const float*)d_in[4];
    const float* W2l = (const float*)d_in[5];
    const float* b2  = (const float*)d_in[6];
    const float* W2r = (const float*)d_in[7];
    const float* W3l = (const float*)d_in[8];
    const float* b3  = (const float*)d_in[9];
    const float* W3r = (const float*)d_in[10];
    float* out = (float*)d_out;

    const int E = in_sizes[1] / 2;
    const int M = in_sizes[0] / DDIM;
    const int* src = ei;
    const int* dst = ei + E;

    __half *xh,*ah,*h1,*h2,*cs;
    __half *w1l,*w1r,*w2l,*w2r,*w3l,*w3r;
    int *deg,*rowptr,*cursor,*csr,*bsums;
    cudaGetSymbolAddress((void**)&xh, g_x);
    cudaGetSymbolAddress((void**)&ah, g_a);
    cudaGetSymbolAddress((void**)&h1, g_h1);
    cudaGetSymbolAddress((void**)&h2, g_h2);
    cudaGetSymbolAddress((void**)&cs, g_cs);
    cudaGetSymbolAddress((void**)&w1l, g_w1l);
    cudaGetSymbolAddress((void**)&w1r, g_w1r);
    cudaGetSymbolAddress((void**)&w2l, g_w2l);
    cudaGetSymbolAddress((void**)&w2r, g_w2r);
    cudaGetSymbolAddress((void**)&w3l, g_w3l);
    cudaGetSymbolAddress((void**)&w3r, g_w3r);
    cudaGetSymbolAddress((void**)&deg,    g_deg);
    cudaGetSymbolAddress((void**)&rowptr, g_rowptr);
    cudaGetSymbolAddress((void**)&cursor, g_cursor);
    cudaGetSymbolAddress((void**)&csr,    g_csr);
    cudaGetSymbolAddress((void**)&bsums,  g_bsums);

    const int nblk = (M + SCAN_B - 1) / SCAN_B;
    const int SMEM_GEMM = 3 * 2 * 128 * 144;  // 110592 B -> 2 CTAs/SM

    // Lazy one-time setup (first call is the uncaptured correctness run).
    static cudaStream_t s2 = nullptr;
    static cudaEvent_t evF, evP, evC, evS1, evJ1, evS2, evJ2, evS3;
    static bool init_done = false;
    if (!init_done) {
        cudaFuncSetAttribute(gemm_mma<0>, cudaFuncAttributeMaxDynamicSharedMemorySize, SMEM_GEMM);
        cudaFuncSetAttribute(gemm_mma<1>, cudaFuncAttributeMaxDynamicSharedMemorySize, SMEM_GEMM);
        cudaFuncSetAttribute(gemm_mma<2>, cudaFuncAttributeMaxDynamicSharedMemorySize, SMEM_GEMM);
        cudaStreamCreateWithFlags(&s2, cudaStreamNonBlocking);
        cudaEventCreateWithFlags(&evF,  cudaEventDisableTiming);
        cudaEventCreateWithFlags(&evP,  cudaEventDisableTiming);
        cudaEventCreateWithFlags(&evC,  cudaEventDisableTiming);
        cudaEventCreateWithFlags(&evS1, cudaEventDisableTiming);
        cudaEventCreateWithFlags(&evJ1, cudaEventDisableTiming);
        cudaEventCreateWithFlags(&evS2, cudaEventDisableTiming);
        cudaEventCreateWithFlags(&evJ2, cudaEventDisableTiming);
        cudaEventCreateWithFlags(&evS3, cudaEventDisableTiming);
        init_done = true;
    }

    const int mTiles  = (M + 127) / 128;
    const int gBlocks = (M + 3) / 4;

    // ======== Fork ========
    cudaEventRecord(evF, 0);
    cudaStreamWaitEvent(s2, evF, 0);

    // s0: prep (convx + weight transposes)
    prep_kernel<<<CONVB + WCONVB, 256, 0, 0>>>(
        (const float4*)x, (uint2*)xh, M * DDIM / 4,
        W1l, W1r, W2l, W2r, W3l, W3r, w1l, w1r, w2l, w2r, w3l, w3r);
    cudaEventRecord(evP, 0);                        // xh + all weights ready

    // s2: self-contained CSR branch (zeroing included; uses only raw inputs)
    zero2_kernel<<<(M + 255) / 256, 256, 0, s2>>>(deg, cursor, M);
    deg_kernel<<<(E + 255) / 256, 256, 0, s2>>>(dst, deg, E);
    scan1_kernel<<<nblk, SCAN_B, 0, s2>>>(deg, rowptr, bsums, M);
    scan3_kernel<<<(M + 255) / 256, 256, 0, s2>>>(rowptr, bsums, nblk, M);
    csr_fill_kernel<<<(E + 255) / 256, 256, 0, s2>>>(src, dst, rowptr, cursor, csr, E);
    cudaEventRecord(evC, s2);                       // CSR ready

    // ======== Layer 1 ========
    // s2: selfgemm cs = xh @ w1r^T   (needs prep)
    cudaStreamWaitEvent(s2, evP, 0);
    gemm_mma<0><<<dim3(4, mTiles), 256, SMEM_GEMM, s2>>>(
        xh, w1r, nullptr, nullptr, nullptr, cs, M, DDIM);
    cudaEventRecord(evS1, s2);

    // s0: gather (needs prep[s0-ordered] + CSR), then combine (needs selfgemm)
    cudaStreamWaitEvent(0, evC, 0);
    gather_mean_kernel<<<gBlocks, 256, 0, 0>>>(xh, rowptr, csr, ah, M);
    cudaStreamWaitEvent(0, evS1, 0);
    gemm_mma<1><<<dim3(4, mTiles), 256, SMEM_GEMM, 0>>>(
        ah, w1l, b1, cs, nullptr, h1, M, DDIM);
    cudaEventRecord(evJ1, 0);                       // h1 ready; cs consumed

    // ======== Layer 2 ========
    cudaStreamWaitEvent(s2, evJ1, 0);
    gemm_mma<0><<<dim3(4, mTiles), 256, SMEM_GEMM, s2>>>(
        h1, w2r, nullptr, nullptr, nullptr, cs, M, DDIM);
    cudaEventRecord(evS2, s2);

    gather_mean_kernel<<<gBlocks, 256, 0, 0>>>(h1, rowptr, csr, ah, M);
    cudaStreamWaitEvent(0, evS2, 0);
    gemm_mma<1><<<dim3(4, mTiles), 256, SMEM_GEMM, 0>>>(
        ah, w2l, b2, cs, nullptr, h2, M, DDIM);
    cudaEventRecord(evJ2, 0);                       // h2 ready; cs consumed

    // ======== Layer 3 ========
    cudaStreamWaitEvent(s2, evJ2, 0);
    gemm_mma<0><<<dim3(1, mTiles), 256, SMEM_GEMM, s2>>>(
        h2, w3r, nullptr, nullptr, nullptr, cs, M, DOUT);
    cudaEventRecord(evS3, s2);

    gather_mean_kernel<<<gBlocks, 256, 0, 0>>>(h2, rowptr, csr, ah, M);
    cudaStreamWaitEvent(0, evS3, 0);                // join s2 back into s0
    gemm_mma<2><<<dim3(1, mTiles), 256, SMEM_GEMM, 0>>>(
        ah, w3l, b3, cs, out, nullptr, M, DOUT);

    // log_softmax in place on d_out
    log_softmax128_kernel<<<(M + 7) / 8, 256, 0, 0>>>(out, M);
    (void)n_in; (void)out_size;
}

// round 16
// speedup vs baseline: 1.1394x; 1.1394x over previous
#include <cuda_runtime.h>
#include <cuda_fp16.h>
#include <cstdint>
#include <cstddef>

#define NN   50000
#define EE   400000
#define DDIM 512
#define DOUT 128
#define SCAN_B 512

// ---------------------------------------------------------------------------
// Scratch (device globals: allocation-free rule)
__device__ __half g_x  [(size_t)NN * DDIM];
__device__ __half g_a  [(size_t)NN * DDIM];
__device__ __half g_h1 [(size_t)NN * DDIM];
__device__ __half g_h2 [(size_t)NN * DDIM];
__device__ __half g_ycs[(size_t)NN * 256];    // L3: [y(128) | cself(128)] per row
// Transposed weights [N][K] fp16
__device__ __half g_w1l[512*512];
__device__ __half g_w1r[512*512];
__device__ __half g_w2l[512*512];
__device__ __half g_w2r[512*512];
__device__ __half g_w3cat[256*512];           // rows 0..127 = W3l^T, 128..255 = W3r^T
// CSR
__device__ int g_deg[NN];
__device__ int g_rowptr[NN + 1];
__device__ int g_cursor[NN];
__device__ int g_csr[EE];
__device__ int g_bsums[(NN + SCAN_B - 1) / SCAN_B + 1];

// ---------------------------------------------------------------------------
// PTX helpers (base-arch only: ldmatrix / mma.sync / cp.async)
// ---------------------------------------------------------------------------
__device__ __forceinline__ uint32_t smem_to_u32(const void* p) {
    uint32_t a;
    asm("{ .reg .u64 t; cvta.to.shared.u64 t, %1; cvt.u32.u64 %0, t; }"
        : "=r"(a) : "l"(p));
    return a;
}

#define LDSM_X4(r0, r1, r2, r3, addr) \
    asm volatile("ldmatrix.sync.aligned.m8n8.x4.shared.b16 {%0,%1,%2,%3}, [%4];" \
        : "=r"(r0), "=r"(r1), "=r"(r2), "=r"(r3) : "r"(addr))

#define MMA_FP16(c, a, bv0, bv1) \
    asm volatile("mma.sync.aligned.m16n8k16.row.col.f32.f16.f16.f32 " \
        "{%0,%1,%2,%3}, {%4,%5,%6,%7}, {%8,%9}, {%0,%1,%2,%3};" \
        : "+f"((c)[0]), "+f"((c)[1]), "+f"((c)[2]), "+f"((c)[3]) \
        : "r"((a)[0]), "r"((a)[1]), "r"((a)[2]), "r"((a)[3]), "r"(bv0), "r"(bv1))

#define CP_ASYNC16(smem, gmem, sz) \
    asm volatile("cp.async.cg.shared.global [%0], [%1], 16, %2;" \
        :: "r"(smem), "l"(gmem), "r"(sz) : "memory")
#define CP_COMMIT() asm volatile("cp.async.commit_group;" ::: "memory")
#define CP_WAIT(n)  asm volatile("cp.async.wait_group %0;" :: "n"(n) : "memory")

// ---------------------------------------------------------------------------
// fp16 helpers
// ---------------------------------------------------------------------------
__device__ __forceinline__ uint32_t pack_h2(float a, float b) {
    __half2 t = __floats2half2_rn(a, b);
    return *reinterpret_cast<uint32_t*>(&t);
}
__device__ __forceinline__ float2 unpack_h2(uint32_t u) {
    __half2 t = *reinterpret_cast<__half2*>(&u);
    return __half22float2(t);
}

// ---------------------------------------------------------------------------
// Fused pre-work kernel: zero + convx + weight transposes
// ---------------------------------------------------------------------------
#define ZEROB  196
#define CONVB  2048
#define WCONVB 1152   // 4*256 (512x512) + 2*64 (512x128)

__global__ void prep_kernel(const float4* __restrict__ x, uint2* __restrict__ xh,
                            int n4, int* __restrict__ deg, int* __restrict__ cursor, int M,
                            const float* __restrict__ W1l, const float* __restrict__ W1r,
                            const float* __restrict__ W2l, const float* __restrict__ W2r,
                            const float* __restrict__ W3l, const float* __restrict__ W3r,
                            __half* __restrict__ o1l, __half* __restrict__ o1r,
                            __half* __restrict__ o2l, __half* __restrict__ o2r,
                            __half* __restrict__ o3cat) {
    __shared__ float t[32][33];
    const int b = blockIdx.x;
    const int tid = threadIdx.x;
    if (b < ZEROB) {
        int i = b * 256 + tid;
        if (i < M) { deg[i] = 0; cursor[i] = 0; }
    } else if (b < ZEROB + CONVB) {
        int i = (b - ZEROB) * 256 + tid;
        const int stride = CONVB * 256;
        for (; i < n4; i += stride) {
            float4 v = x[i];
            uint2 u;
            u.x = pack_h2(v.x, v.y);
            u.y = pack_h2(v.z, v.w);
            xh[i] = u;
        }
    } else {
        int wb = b - ZEROB - CONVB;
        const float* W; __half* O; int N, idx;
        if (wb < 1024) {
            int z = wb >> 8; idx = wb & 255; N = 512;
            W = (z == 0) ? W1l : (z == 1) ? W1r : (z == 2) ? W2l : W2r;
            O = (z == 0) ? o1l : (z == 1) ? o1r : (z == 2) ? o2l : o2r;
        } else {
            int wb2 = wb - 1024; int z = wb2 >> 6; idx = wb2 & 63; N = 128;
            W = z ? W3r : W3l;
            O = o3cat + (z ? 128 * 512 : 0);   // W3r rows land at 128..255
        }
        const int nXb = N >> 5;
        int nb = (idx % nXb) * 32, kb = (idx / nXb) * 32;
        int tx = tid & 31, ty = tid >> 5;
        for (int i = ty; i < 32; i += 8)
            t[i][tx] = W[(size_t)(kb + i) * N + nb + tx];
        __syncthreads();
        for (int i = ty; i < 32; i += 8) {
            float v = t[tx][i];
            O[(size_t)(nb + i) * 512 + kb + tx] = __float2half_rn(v);
        }
    }
}

// ---------------------------------------------------------------------------
// CSR construction
// ---------------------------------------------------------------------------
__global__ void deg_kernel(const int* __restrict__ dst, int* __restrict__ deg, int E) {
    int e = blockIdx.x * blockDim.x + threadIdx.x;
    if (e < E) atomicAdd(&deg[dst[e]], 1);
}
__global__ void scan1_kernel(const int* __restrict__ deg, int* __restrict__ rowptr,
                             int* __restrict__ bsums, int M) {
    __shared__ int sh[SCAN_B];
    int tid = threadIdx.x;
    int i = blockIdx.x * SCAN_B + tid;
    int v = (i < M) ? deg[i] : 0;
    sh[tid] = v;
    __syncthreads();
#pragma unroll
    for (int off = 1; off < SCAN_B; off <<= 1) {
        int t = (tid >= off) ? sh[tid - off] : 0;
        __syncthreads();
        sh[tid] += t;
        __syncthreads();
    }
    if (i < M) rowptr[i] = sh[tid] - v;
    if (tid == SCAN_B - 1) bsums[blockIdx.x] = sh[tid];
}
__global__ void scan3_kernel(int* __restrict__ rowptr, const int* __restrict__ bsums,
                             int nblk, int M) {
    __shared__ int sh[256];
    const int tid = threadIdx.x;
    const int chunk = blockIdx.x >> 1;
    int partial = 0;
    for (int j = tid; j < chunk; j += 256) partial += bsums[j];
    sh[tid] = partial;
    __syncthreads();
#pragma unroll
    for (int off = 128; off; off >>= 1) {
        if (tid < off) sh[tid] += sh[tid + off];
        __syncthreads();
    }
    const int off = sh[0];
    int i = blockIdx.x * 256 + tid;
    if (i < M) rowptr[i] += off;
    if (blockIdx.x == 0 && tid == 0) {
        int tot = 0;
        for (int j = 0; j < nblk; j++) tot += bsums[j];
        rowptr[M] = tot;
    }
}
__global__ void csr_fill_kernel(const int* __restrict__ src, const int* __restrict__ dst,
                                const int* __restrict__ rowptr, int* __restrict__ cursor,
                                int* __restrict__ csr, int E) {
    int e = blockIdx.x * blockDim.x + threadIdx.x;
    if (e < E) {
        int d = dst[e];
        int pos = atomicAdd(&cursor[d], 1);
        csr[rowptr[d] + pos] = src[e];
    }
}

// ---------------------------------------------------------------------------
// Gather-mean on fp16 (512-dim): 4 nodes per block, 64 threads per node,
// one uint4 (8 halves) per thread; 8-deep unroll.
// ---------------------------------------------------------------------------
__global__ void gather_mean_kernel(const __half* __restrict__ xh,
                                   const int* __restrict__ rowptr,
                                   const int* __restrict__ csr,
                                   __half* __restrict__ ah, int M) {
    int node = blockIdx.x * 4 + (threadIdx.x >> 6);
    int t    = threadIdx.x & 63;
    if (node >= M) return;
    int beg = rowptr[node], end = rowptr[node + 1];
    const uint4* XH = (const uint4*)xh;
    float a[8];
#pragma unroll
    for (int j = 0; j < 8; j++) a[j] = 0.f;

    auto accum = [&](uint4 u) {
        float2 p;
        p = unpack_h2(u.x); a[0] += p.x; a[1] += p.y;
        p = unpack_h2(u.y); a[2] += p.x; a[3] += p.y;
        p = unpack_h2(u.z); a[4] += p.x; a[5] += p.y;
        p = unpack_h2(u.w); a[6] += p.x; a[7] += p.y;
    };

    int i = beg;
    for (; i + 7 < end; i += 8) {
        uint4 v0 = XH[(size_t)csr[i+0] * 64 + t];
        uint4 v1 = XH[(size_t)csr[i+1] * 64 + t];
        uint4 v2 = XH[(size_t)csr[i+2] * 64 + t];
        uint4 v3 = XH[(size_t)csr[i+3] * 64 + t];
        uint4 v4 = XH[(size_t)csr[i+4] * 64 + t];
        uint4 v5 = XH[(size_t)csr[i+5] * 64 + t];
        uint4 v6 = XH[(size_t)csr[i+6] * 64 + t];
        uint4 v7 = XH[(size_t)csr[i+7] * 64 + t];
        accum(v0); accum(v1); accum(v2); accum(v3);
        accum(v4); accum(v5); accum(v6); accum(v7);
    }
    for (; i + 3 < end; i += 4) {
        uint4 v0 = XH[(size_t)csr[i+0] * 64 + t];
        uint4 v1 = XH[(size_t)csr[i+1] * 64 + t];
        uint4 v2 = XH[(size_t)csr[i+2] * 64 + t];
        uint4 v3 = XH[(size_t)csr[i+3] * 64 + t];
        accum(v0); accum(v1); accum(v2); accum(v3);
    }
    for (; i < end; i++) accum(XH[(size_t)csr[i] * 64 + t]);

    float inv = 1.0f / (float)max(end - beg, 1);
    uint4 u;
    uint32_t* pu = (uint32_t*)&u;
#pragma unroll
    for (int j = 0; j < 4; j++)
        pu[j] = pack_h2(a[j*2+0] * inv, a[j*2+1] * inv);
    ((uint4*)ah)[(size_t)node * 64 + t] = u;
}

// ---------------------------------------------------------------------------
// mma.sync fp16 GEMM, 3-stage cp.async pipeline.
// C[M, Ntot] = A0 @ B0^T (+ A1 @ B1^T if NCH=16)   (each K half 512)
// NCH=16: K=1024 split across (A0,B0)/(A1,B1). NCH=8: K=512, A1/B1 unused.
// MODE 0: raw fp16 store (no bias). MODE 1: +bias, ReLU, fp16 store.
// CTA tile 128x128, 8 warps (4m x 2n), fp32 accumulators. SROW=144.
// ---------------------------------------------------------------------------
template <int NCH, int MODE>
__global__ __launch_bounds__(256, 2)
void gemm_mma(const __half* __restrict__ A0, const __half* __restrict__ A1,
              const __half* __restrict__ B0, const __half* __restrict__ B1,
              const float* __restrict__ bias,
              __half* __restrict__ Ch, int M, int Ntot) {
    extern __shared__ char dsm[];
    constexpr int SROW  = 144;
    constexpr int PLANE = 128 * SROW;  // 18432 B
    constexpr int STAGE = 2 * PLANE;   // 36864 B: A, B
    constexpr int NSTAGE = 3;          // 110592 B -> 2 CTAs/SM
    constexpr int OFF_A = 0, OFF_B = PLANE;

    const int tid  = threadIdx.x;
    const int wid  = tid >> 5;
    const int lane = tid & 31;
    const int wm = wid >> 1;
    const int wn = wid & 1;
    const int mBase = blockIdx.y * 128;
    const int nBase = blockIdx.x * 128;
    const uint32_t smem = smem_to_u32(dsm);

    auto issue_chunk = [&](int ch, int s) {
        const bool half = (ch >= 8);
        const char* Ap = (const char*)(half ? A1 : A0);
        const char* Bp = (const char*)(half ? B1 : B0);
        const int k0b = (ch & 7) * 128;
        const uint32_t sb = smem + s * STAGE;
#pragma unroll
        for (int it = 0; it < 4; it++) {
            int c = tid + it * 256;
            int row = c >> 3, q = c & 7;
            uint32_t soff = row * SROW + q * 16;
            int am = mBase + row;
            int asz = (am < M) ? 16 : 0;
            size_t ga = (size_t)(am < M ? am : 0) * 1024 + k0b + q * 16;
            CP_ASYNC16(sb + OFF_A + soff, Ap + ga, asz);
            size_t gb = (size_t)(nBase + row) * 1024 + k0b + q * 16;
            CP_ASYNC16(sb + OFF_B + soff, Bp + gb, 16);
        }
        CP_COMMIT();
    };

    float acc[2][8][4];
#pragma unroll
    for (int i = 0; i < 2; i++)
#pragma unroll
        for (int j = 0; j < 8; j++)
#pragma unroll
            for (int k = 0; k < 4; k++) acc[i][j][k] = 0.f;

    const int g = lane >> 3, r = lane & 7;

    issue_chunk(0, 0);
    issue_chunk(1, 1);
    for (int ch = 0; ch < NCH; ch++) {
        const int s = ch % NSTAGE;
        if (ch + 1 < NCH) { CP_WAIT(1); } else { CP_WAIT(0); }
        __syncthreads();
        if (ch + 2 < NCH) issue_chunk(ch + 2, (ch + 2) % NSTAGE);

        const uint32_t sA = smem + s * STAGE + OFF_A;
        const uint32_t sB = smem + s * STAGE + OFF_B;

#pragma unroll
        for (int ks = 0; ks < 4; ks++) {
            uint32_t ah[2][4];
#pragma unroll
            for (int mi = 0; mi < 2; mi++) {
                uint32_t arow = wm * 32 + mi * 16 + ((g & 1) << 3) + r;
                uint32_t aoff = arow * SROW + ks * 32 + (g >> 1) * 16;
                LDSM_X4(ah[mi][0], ah[mi][1], ah[mi][2], ah[mi][3], sA + aoff);
            }
#pragma unroll
            for (int j = 0; j < 4; j++) {
                uint32_t brow = wn * 64 + j * 16 + ((g >> 1) << 3) + r;
                uint32_t boff = brow * SROW + ks * 32 + (g & 1) * 16;
                uint32_t b0, b1, b2, b3;
                LDSM_X4(b0, b1, b2, b3, sB + boff);
                MMA_FP16(acc[0][j*2+0], ah[0], b0, b1);
                MMA_FP16(acc[0][j*2+1], ah[0], b2, b3);
                MMA_FP16(acc[1][j*2+0], ah[1], b0, b1);
                MMA_FP16(acc[1][j*2+1], ah[1], b2, b3);
            }
        }
    }

    // ---- Epilogue ----
    const int qrow = lane >> 2, qcol = lane & 3;
#pragma unroll
    for (int mi = 0; mi < 2; mi++) {
#pragma unroll
        for (int ni = 0; ni < 8; ni++) {
            int row0 = mBase + wm * 32 + mi * 16 + qrow;
            int col  = nBase + wn * 64 + ni * 8 + qcol * 2;
#pragma unroll
            for (int h = 0; h < 2; h++) {
                int row = row0 + h * 8;
                if (row >= M) continue;
                float v0 = acc[mi][ni][h*2+0];
                float v1 = acc[mi][ni][h*2+1];
                if (MODE == 1) {
                    float2 bb = *(const float2*)(bias + col);
                    v0 = fmaxf(v0 + bb.x, 0.f);
                    v1 = fmaxf(v1 + bb.y, 0.f);
                }
                *(uint32_t*)(Ch + (size_t)row * Ntot + col) = pack_h2(v0, v1);
            }
        }
    }
}

// ---------------------------------------------------------------------------
// L3 fused gather + combine + log_softmax.
// ycs rows: [y(128 fp16) | cself(128 fp16)], stride 256 halves (64 uint2).
// One warp per node: lane handles 4 dims (uint2 per neighbor = 4 halves).
// out[node] = log_softmax( mean_j y[j] + cself[node] + bias ).
// ---------------------------------------------------------------------------
__global__ void gather_softmax_kernel(const __half* __restrict__ ycs,
                                      const int* __restrict__ rowptr,
                                      const int* __restrict__ csr,
                                      const float* __restrict__ bias,
                                      float* __restrict__ out, int M) {
    int node = blockIdx.x * 8 + (threadIdx.x >> 5);
    int lane = threadIdx.x & 31;
    if (node >= M) return;
    int beg = rowptr[node], end = rowptr[node + 1];
    const uint2* Y = (const uint2*)ycs;     // 64 uint2 per row; y = first 32

    float a0 = 0.f, a1 = 0.f, a2 = 0.f, a3 = 0.f;
    auto accum = [&](uint2 u) {
        float2 p;
        p = unpack_h2(u.x); a0 += p.x; a1 += p.y;
        p = unpack_h2(u.y); a2 += p.x; a3 += p.y;
    };

    int i = beg;
    for (; i + 7 < end; i += 8) {
        uint2 v0 = Y[(size_t)csr[i+0] * 64 + lane];
        uint2 v1 = Y[(size_t)csr[i+1] * 64 + lane];
        uint2 v2 = Y[(size_t)csr[i+2] * 64 + lane];
        uint2 v3 = Y[(size_t)csr[i+3] * 64 + lane];
        uint2 v4 = Y[(size_t)csr[i+4] * 64 + lane];
        uint2 v5 = Y[(size_t)csr[i+5] * 64 + lane];
        uint2 v6 = Y[(size_t)csr[i+6] * 64 + lane];
        uint2 v7 = Y[(size_t)csr[i+7] * 64 + lane];
        accum(v0); accum(v1); accum(v2); accum(v3);
        accum(v4); accum(v5); accum(v6); accum(v7);
    }
    for (; i < end; i++) accum(Y[(size_t)csr[i] * 64 + lane]);

    float inv = 1.0f / (float)max(end - beg, 1);
    // self term + bias
    uint2 cu = Y[(size_t)node * 64 + 32 + lane];
    float2 c0 = unpack_h2(cu.x), c1 = unpack_h2(cu.y);
    float4 bb = ((const float4*)bias)[lane];
    float v0 = a0 * inv + c0.x + bb.x;
    float v1 = a1 * inv + c0.y + bb.y;
    float v2 = a2 * inv + c1.x + bb.z;
    float v3 = a3 * inv + c1.y + bb.w;

    // warp log_softmax over 128 values
    float mx = fmaxf(fmaxf(v0, v1), fmaxf(v2, v3));
#pragma unroll
    for (int o = 16; o; o >>= 1) mx = fmaxf(mx, __shfl_xor_sync(0xffffffffu, mx, o));
    float s = expf(v0 - mx) + expf(v1 - mx) + expf(v2 - mx) + expf(v3 - mx);
#pragma unroll
    for (int o = 16; o; o >>= 1) s += __shfl_xor_sync(0xffffffffu, s, o);
    float l = mx + logf(s);
    float4 o4;
    o4.x = v0 - l; o4.y = v1 - l; o4.z = v2 - l; o4.w = v3 - l;
    ((float4*)out)[(size_t)node * 32 + lane] = o4;
}

// ---------------------------------------------------------------------------
extern "C" void kernel_launch(void* const* d_in, const int* in_sizes, int n_in,
                              void* d_out, int out_size) {
    const float* x   = (const float*)d_in[0];
    const int*   ei  = (const int*)  d_in[1];
    const float* W1l = (const float*)d_in[2];
    const float* b1  = (const float*)d_in[3];
    const float* W1r = (const float*)d_in[4];
    const float* W2l = (const float*)d_in[5];
    const float* b2  = (const float*)d_in[6];
    const float* W2r = (const float*)d_in[7];
    const float* W3l = (const float*)d_in[8];
    const float* b3  = (const float*)d_in[9];
    const float* W3r = (const float*)d_in[10];
    float* out = (float*)d_out;

    const int E = in_sizes[1] / 2;
    const int M = in_sizes[0] / DDIM;
    const int* src = ei;
    const int* dst = ei + E;

    __half *xh,*ah,*h1,*h2,*ycs;
    __half *w1l,*w1r,*w2l,*w2r,*w3cat;
    int *deg,*rowptr,*cursor,*csr,*bsums;
    cudaGetSymbolAddress((void**)&xh, g_x);
    cudaGetSymbolAddress((void**)&ah, g_a);
    cudaGetSymbolAddress((void**)&h1, g_h1);
    cudaGetSymbolAddress((void**)&h2, g_h2);
    cudaGetSymbolAddress((void**)&ycs, g_ycs);
    cudaGetSymbolAddress((void**)&w1l, g_w1l);
    cudaGetSymbolAddress((void**)&w1r, g_w1r);
    cudaGetSymbolAddress((void**)&w2l, g_w2l);
    cudaGetSymbolAddress((void**)&w2r, g_w2r);
    cudaGetSymbolAddress((void**)&w3cat, g_w3cat);
    cudaGetSymbolAddress((void**)&deg,    g_deg);
    cudaGetSymbolAddress((void**)&rowptr, g_rowptr);
    cudaGetSymbolAddress((void**)&cursor, g_cursor);
    cudaGetSymbolAddress((void**)&csr,    g_csr);
    cudaGetSymbolAddress((void**)&bsums,  g_bsums);

    const int nblk = (M + SCAN_B - 1) / SCAN_B;

    const int SMEM_GEMM = 3 * 2 * 128 * 144;  // 110592 B -> 2 CTAs/SM
    cudaFuncSetAttribute(gemm_mma<16,1>, cudaFuncAttributeMaxDynamicSharedMemorySize, SMEM_GEMM);
    cudaFuncSetAttribute(gemm_mma<8,0>,  cudaFuncAttributeMaxDynamicSharedMemorySize, SMEM_GEMM);

    // ---- Fused pre-work: zero + convx + all weight transposes (one launch) ----
    prep_kernel<<<ZEROB + CONVB + WCONVB, 256>>>(
        (const float4*)x, (uint2*)xh, M * DDIM / 4, deg, cursor, M,
        W1l, W1r, W2l, W2r, W3l, W3r, w1l, w1r, w2l, w2r, w3cat);

    // ---- CSR build ----
    deg_kernel<<<(E + 255) / 256, 256>>>(dst, deg, E);
    scan1_kernel<<<nblk, SCAN_B>>>(deg, rowptr, bsums, M);
    scan3_kernel<<<(M + 255) / 256, 256>>>(rowptr, bsums, nblk, M);
    csr_fill_kernel<<<(E + 255) / 256, 256>>>(src, dst, rowptr, cursor, csr, E);

    const int mTiles = (M + 127) / 128;
    const int gBlocks = (M + 3) / 4;

    // ---- Layer 1 ----
    gather_mean_kernel<<<gBlocks, 256>>>(xh, rowptr, csr, ah, M);
    gemm_mma<16,1><<<dim3(4, mTiles), 256, SMEM_GEMM>>>(
        ah, xh, w1l, w1r, b1, h1, M, DDIM);

    // ---- Layer 2 ----
    gather_mean_kernel<<<gBlocks, 256>>>(h1, rowptr, csr, ah, M);
    gemm_mma<16,1><<<dim3(4, mTiles), 256, SMEM_GEMM>>>(
        ah, h1, w2l, w2r, b2, h2, M, DDIM);

    // ---- Layer 3: transform-then-gather (mean is linear) ----
    // [y | cs] = h2 @ [W3l ; W3r]^T  (N=256, K=512)
    gemm_mma<8,0><<<dim3(2, mTiles), 256, SMEM_GEMM>>>(
        h2, h2, w3cat, w3cat, nullptr, ycs, M, 256);
    // out = log_softmax( gather-mean(y) + cs + b3 )
    gather_softmax_kernel<<<(M + 7) / 8, 256>>>(ycs, rowptr, csr, b3, out, M);

    (void)n_in; (void)out_size;
}